// round 10
// baseline (speedup 1.0000x reference)
#include <cuda_runtime.h>
#include <cuda_fp16.h>

// TrainableActivation (per-channel RBF activation) on GB300 — round 10.
//
// out[n,c,h,w] = sum_{j=0..30} w[c,j] * exp(-112.5 * (x - mu_j)^2)
//
// Round-10 = round-9 L2-steering theory with the sm_103a-legal encoding:
// ptxas only allows .L2::evict_* on 256-bit vectors (.v8.b32/.v4.b64).
//  * x loads:  ld.global.L2::evict_last.v8.b32  (x -> L2-resident; 67MB
//    input fits the 126MB L2 and is re-read every graph replay)
//  * y stores: st.global.L2::evict_first.v8.b32 (write-once stream)
//  * bonus: 32B/thread accesses halve LDG/STG instruction count.
// Rest as round 7/9: fused single kernel, fully-resident 1024-block wave,
// windowed Gaussian-lattice LUT build, 8-way bank-replicated fp16 LUT,
// depth-2 register pipeline (2 x 32B x 56 warps/SM >> Little's law).

#define NUM_CH   64
#define NUM_W    31
#define LUT_N    512
#define REP      8
#define HW       16384    // 128*128 floats per plane
#define NBATCH   16

#define CHUNK_FLOATS  8        // 32 B per thread per step
#define STEPS         8        // 16384 / (256*8)
#define DEPTH         2        // register pipeline depth

struct F8 { float4 a, b; };

__device__ __forceinline__ F8 ldg256_evict_last(const float* p)
{
    F8 v;
    asm volatile(
        "ld.global.L2::evict_last.v8.b32 {%0,%1,%2,%3,%4,%5,%6,%7}, [%8];"
        : "=f"(v.a.x), "=f"(v.a.y), "=f"(v.a.z), "=f"(v.a.w),
          "=f"(v.b.x), "=f"(v.b.y), "=f"(v.b.z), "=f"(v.b.w)
        : "l"(p));
    return v;
}
__device__ __forceinline__ void stg256_evict_first(float* p, const F8& v)
{
    asm volatile(
        "st.global.L2::evict_first.v8.b32 [%0], {%1,%2,%3,%4,%5,%6,%7,%8};"
        :: "l"(p),
           "f"(v.a.x), "f"(v.a.y), "f"(v.a.z), "f"(v.a.w),
           "f"(v.b.x), "f"(v.b.y), "f"(v.b.z), "f"(v.b.w)
        : "memory");
}

__global__ void __launch_bounds__(256, 7)
fused_rbf_kernel(const float* __restrict__ x,
                 float* __restrict__ y,
                 const float* __restrict__ w)
{
    __shared__ __align__(16) __half2 lut[LUT_N * REP];  // 16 KB, 8-way replicated
    __shared__ float fv[LUT_N + 1];                     //  2 KB raw values
    __shared__ float ws[NUM_W];

    const int c   = blockIdx.x;
    const int n   = blockIdx.y;
    const int tid = threadIdx.x;

    const float* src = x + (size_t)(n * NUM_CH + c) * HW + tid * CHUNK_FLOATS;
    float*       dst = y + (size_t)(n * NUM_CH + c) * HW + tid * CHUNK_FLOATS;

    // ---- Prologue: get DRAM going before anything else -------------------
    F8 vb[DEPTH];
#pragma unroll
    for (int t = 0; t < DEPTH; t++)
        vb[t] = ldg256_evict_last(src + t * (256 * CHUNK_FLOATS));

    // ---- Build this channel's LUT (hides under the LDG latency) ----------
    if (tid < NUM_W) ws[tid] = w[c * NUM_W + tid];
    __syncthreads();

    // f at 513 points over [-1.5,1.5]; 11-center window + lattice recurrence
    // (sigma == spacing): g_{j+1} = g_j*r_j, r_{j+1} = r_j*e^-1.
    const float h = 3.0f / (float)(LUT_N - 1);
    for (int k = tid; k < LUT_N + 1; k += 256) {
        const float xx = fmaf((float)k, h, -1.5f);
        int j0 = (int)ceilf((xx + 1.0f) * 15.0f - 5.4f);
        j0 = min(20, max(0, j0));
        const float u0 = xx - fmaf((float)j0, 1.0f / 15.0f, -1.0f);

        float g = __expf(-112.5f * u0 * u0);
        float r = __expf(fmaf(15.0f, u0, -0.5f));
        float s = 0.0f;
#pragma unroll
        for (int m = 0; m < 11; m++) {
            s = fmaf(ws[j0 + m], g, s);
            g *= r;
            r *= 0.36787944f;    // e^-1
        }
        fv[k] = s;
    }
    __syncthreads();

    // Pack (value, forward-delta) half2; replicate 8-way:
    // entry i occupies words 8i..8i+7 (lane reads copy lane&7).
#pragma unroll
    for (int m = 0; m < LUT_N / 256; m++) {
        const int i = tid + 256 * m;
        __half2 e = __floats2half2_rn(fv[i], fv[i + 1] - fv[i]);
        const unsigned u = *reinterpret_cast<unsigned*>(&e);
        const uint4 q = make_uint4(u, u, u, u);
        reinterpret_cast<uint4*>(lut)[2 * i]     = q;
        reinterpret_cast<uint4*>(lut)[2 * i + 1] = q;
    }
    __syncthreads();   // last barrier; main loop is barrier-free

    // ---- Main loop: 8 steps x 8 floats through the register pipeline -----
    const float INV_H = (float)(LUT_N - 1) / 3.0f;
    const float OFF   = 1.5f * INV_H;
    const float TMAX  = (float)(LUT_N - 1);

    const __half2* lp = lut + (tid & 7);

#pragma unroll
    for (int t = 0; t < STEPS; t++) {
        const F8 v = vb[t % DEPTH];
        if (t + DEPTH < STEPS)                            // refill the slot
            vb[t % DEPTH] = ldg256_evict_last(src + (t + DEPTH) * (256 * CHUNK_FLOATS));

        F8 o;
        const float* vi = &v.a.x;
        float*       oi = &o.a.x;
#pragma unroll
        for (int e8 = 0; e8 < 8; e8++) {
            const float tt = fminf(fmaxf(fmaf(vi[e8], INV_H, OFF), 0.0f), TMAX);
            const int idx = (int)tt;
            const float2 e = __half22float2(lp[idx * REP]);
            oi[e8] = fmaf(tt - (float)idx, e.y, e.x);
        }

        stg256_evict_first(dst + t * (256 * CHUNK_FLOATS), o);
    }
}

// ---------------------------------------------------------------------------
// Launch: ONE kernel (graph-capturable, allocation-free, deterministic).
// ---------------------------------------------------------------------------
extern "C" void kernel_launch(void* const* d_in, const int* in_sizes, int n_in,
                              void* d_out, int out_size)
{
    const float* x = (const float*)d_in[0];   // [16, 64, 128, 128] fp32
    const float* w = (const float*)d_in[1];   // [64, 31] fp32

    fused_rbf_kernel<<<dim3(NUM_CH, NBATCH), 256>>>(x, (float*)d_out, w);
}

// round 11
// speedup vs baseline: 1.1099x; 1.1099x over previous
#include <cuda_runtime.h>
#include <cuda_fp16.h>

// TrainableActivation (per-channel RBF activation) on GB300 — round 11.
//
// out[n,c,h,w] = sum_{j=0..30} w[c,j] * exp(-112.5 * (x - mu_j)^2)
//
// Round-11: revert round-10's 256-bit/evict experiment (regression: 23.6us,
// L2-steering falsified). This is round 7 — the proven best (21.2us total,
// 19.46us kernel) — plus 8-way LUT replication.
//
// Ceiling analysis (rounds 5-8): four structurally disjoint implementations
// all pin at ~19.5us kernel = 134MB / ~6300 B/cyc full-chip LTS cap. The
// binder is the L2 crossbar (all 134MB app traffic must traverse LTS);
// traffic is irreducible (fp32 in/out, single pass). 19.5us IS the roofline.
//
//  * fused single kernel: windowed Gaussian-lattice LUT build (2 __expf +
//    11 fma-pairs per entry) hides under the prologue LDG latency
//  * 512-entry half2 (value,delta) LUT, 8-WAY bank-replicated (words
//    8i..8i+7, lane reads copy lane&7) -> gather replay ~1.9
//  * grid (64,16) = 1024 blocks, launch_bounds(256,7): fully resident wave
//  * depth-3 register input pipeline, streaming (__stcs) stores

#define NUM_CH   64
#define NUM_W    31
#define LUT_N    512
#define REP      8
#define HW       16384    // 128*128
#define NBATCH   16

#define TILE_F4       256      // float4 per tile == blockDim
#define TILES_PER_BLK 16       // one full plane: 4096 float4
#define DEPTH         3        // register pipeline depth

__global__ void __launch_bounds__(256, 7)
fused_rbf_kernel(const float4* __restrict__ x,
                 float4* __restrict__ y,
                 const float* __restrict__ w)
{
    __shared__ __align__(16) __half2 lut[LUT_N * REP];  // 16 KB, 8-way replicated
    __shared__ float fv[LUT_N + 1];                     //  2 KB raw values
    __shared__ float ws[NUM_W];

    const int c   = blockIdx.x;
    const int n   = blockIdx.y;
    const int tid = threadIdx.x;

    const int base = (n * NUM_CH + c) * (HW / 4);
    const float4* src = x + base;
    float4*       dst = y + base;

    // ---- Prologue: get DRAM going before anything else -------------------
    float4 vb[DEPTH];
#pragma unroll
    for (int t = 0; t < DEPTH; t++)
        vb[t] = src[t * TILE_F4 + tid];

    // ---- Build this channel's LUT (hides under the LDG latency) ----------
    if (tid < NUM_W) ws[tid] = w[c * NUM_W + tid];
    __syncthreads();

    // f at 513 points over [-1.5,1.5]; 11-center window + lattice recurrence
    // (sigma == spacing): g_{j+1} = g_j*r_j, r_{j+1} = r_j*e^-1.
    const float h = 3.0f / (float)(LUT_N - 1);
    for (int k = tid; k < LUT_N + 1; k += 256) {
        const float xx = fmaf((float)k, h, -1.5f);
        int j0 = (int)ceilf((xx + 1.0f) * 15.0f - 5.4f);
        j0 = min(20, max(0, j0));
        const float u0 = xx - fmaf((float)j0, 1.0f / 15.0f, -1.0f);

        float g = __expf(-112.5f * u0 * u0);
        float r = __expf(fmaf(15.0f, u0, -0.5f));
        float s = 0.0f;
#pragma unroll
        for (int m = 0; m < 11; m++) {
            s = fmaf(ws[j0 + m], g, s);
            g *= r;
            r *= 0.36787944f;    // e^-1
        }
        fv[k] = s;
    }
    __syncthreads();

    // Pack (value, forward-delta) half2; replicate 8-way:
    // entry i occupies words 8i..8i+7 (lane reads copy lane&7).
#pragma unroll
    for (int m = 0; m < LUT_N / 256; m++) {
        const int i = tid + 256 * m;
        __half2 e = __floats2half2_rn(fv[i], fv[i + 1] - fv[i]);
        const unsigned u = *reinterpret_cast<unsigned*>(&e);
        const uint4 q = make_uint4(u, u, u, u);
        reinterpret_cast<uint4*>(lut)[2 * i]     = q;
        reinterpret_cast<uint4*>(lut)[2 * i + 1] = q;
    }
    __syncthreads();   // last barrier; main loop is barrier-free

    // ---- Main loop: 16 tiles through the register pipeline ---------------
    const float INV_H = (float)(LUT_N - 1) / 3.0f;
    const float OFF   = 1.5f * INV_H;
    const float TMAX  = (float)(LUT_N - 1);

    const __half2* lp = lut + (tid & 7);

#pragma unroll
    for (int t = 0; t < TILES_PER_BLK; t++) {
        const float4 v = vb[t % DEPTH];
        if (t + DEPTH < TILES_PER_BLK)                    // refill the slot
            vb[t % DEPTH] = src[(t + DEPTH) * TILE_F4 + tid];

        float4 o;
        {
            const float tt = fminf(fmaxf(fmaf(v.x, INV_H, OFF), 0.0f), TMAX);
            const int idx = (int)tt;
            const float2 e = __half22float2(lp[idx * REP]);
            o.x = fmaf(tt - (float)idx, e.y, e.x);
        }
        {
            const float tt = fminf(fmaxf(fmaf(v.y, INV_H, OFF), 0.0f), TMAX);
            const int idx = (int)tt;
            const float2 e = __half22float2(lp[idx * REP]);
            o.y = fmaf(tt - (float)idx, e.y, e.x);
        }
        {
            const float tt = fminf(fmaxf(fmaf(v.z, INV_H, OFF), 0.0f), TMAX);
            const int idx = (int)tt;
            const float2 e = __half22float2(lp[idx * REP]);
            o.z = fmaf(tt - (float)idx, e.y, e.x);
        }
        {
            const float tt = fminf(fmaxf(fmaf(v.w, INV_H, OFF), 0.0f), TMAX);
            const int idx = (int)tt;
            const float2 e = __half22float2(lp[idx * REP]);
            o.w = fmaf(tt - (float)idx, e.y, e.x);
        }

        __stcs(dst + t * TILE_F4 + tid, o);
    }
}

// ---------------------------------------------------------------------------
// Launch: ONE kernel (graph-capturable, allocation-free, deterministic).
// ---------------------------------------------------------------------------
extern "C" void kernel_launch(void* const* d_in, const int* in_sizes, int n_in,
                              void* d_out, int out_size)
{
    const float* x = (const float*)d_in[0];   // [16, 64, 128, 128] fp32
    const float* w = (const float*)d_in[1];   // [64, 31] fp32

    fused_rbf_kernel<<<dim3(NUM_CH, NBATCH), 256>>>(
        reinterpret_cast<const float4*>(x),
        reinterpret_cast<float4*>(d_out),
        w);
}